// round 1
// baseline (speedup 1.0000x reference)
#include <cuda_runtime.h>

// Max pool 2x2 stride 2, NCHW (32,128,224,224) fp32 -> (32,128,112,112)
// Pure streaming: in 822MB + out 206MB, HBM-bound.
//
// Each thread: 2 output pixels along W.
//   loads float4 from input row 2*oh and row 2*oh+1 at col 4*ow2
//   writes float2 at output (oh, 2*ow2)
// All accesses 16B/8B aligned (row strides 896B / 448B).

#define IW  224
#define IH  224
#define OW  112
#define OH  112
#define OW2 56          // float2 pairs per output row
#define NC  (32 * 128)

__global__ __launch_bounds__(256, 8)
void pool2d_kernel(const float* __restrict__ in, float2* __restrict__ out) {
    const long long tid = (long long)blockIdx.x * blockDim.x + threadIdx.x;
    // total pair-outputs = NC * OH * OW2 = 4096*112*56 = 25,690,112
    const int p   = (int)tid;                // fits in int (25.7M < 2^31)
    const int ow2 = p % OW2;
    const int t1  = p / OW2;
    const int oh  = t1 % OH;
    const int nc  = t1 / OH;

    const long long base = (long long)nc * (IH * IW) + (long long)(2 * oh) * IW + 4 * ow2;
    const float4 a = *reinterpret_cast<const float4*>(in + base);
    const float4 b = *reinterpret_cast<const float4*>(in + base + IW);

    float2 r;
    r.x = fmaxf(fmaxf(a.x, a.y), fmaxf(b.x, b.y));
    r.y = fmaxf(fmaxf(a.z, a.w), fmaxf(b.z, b.w));

    out[(long long)nc * (OH * OW2) + (long long)oh * OW2 + ow2] = r;
}

extern "C" void kernel_launch(void* const* d_in, const int* in_sizes, int n_in,
                              void* d_out, int out_size) {
    const float* x = (const float*)d_in[0];
    float2* out = (float2*)d_out;

    const long long total_pairs = (long long)NC * OH * OW2;  // 25,690,112
    const int threads = 256;
    const int blocks = (int)((total_pairs + threads - 1) / threads);  // 100,352

    pool2d_kernel<<<blocks, threads>>>(x, out);
}

// round 2
// speedup vs baseline: 1.0223x; 1.0223x over previous
#include <cuda_runtime.h>

// Max pool 2x2 stride 2, NCHW (32,128,224,224) fp32 -> (32,128,112,112)
// HBM-bound streaming kernel: 822MB read + 206MB write.
//
// R2: 4 output pixels per thread (float4 store), 4 independent float4 loads
// (2 per input row), streaming cache hints (.cs) since data is touched once.

#define IW  224
#define IH  224
#define OW  112
#define OH  112
#define OW4 28          // float4 quads per output row (112/4)
#define NC  (32 * 128)

__global__ __launch_bounds__(256, 8)
void pool2d_kernel(const float* __restrict__ in, float4* __restrict__ out) {
    const int p = blockIdx.x * blockDim.x + threadIdx.x;
    // total quad-outputs = NC * OH * OW4 = 4096*112*28 = 12,845,056
    const int ow4 = p % OW4;
    const int t1  = p / OW4;
    const int oh  = t1 % OH;
    const int nc  = t1 / OH;

    const long long base = (long long)nc * (IH * IW) + (long long)(2 * oh) * IW + 8 * ow4;
    const float4* p0 = reinterpret_cast<const float4*>(in + base);
    const float4* p1 = reinterpret_cast<const float4*>(in + base + IW);

    // 4 independent loads issued up front (MLP=4)
    const float4 a0 = __ldcs(p0);
    const float4 a1 = __ldcs(p0 + 1);
    const float4 b0 = __ldcs(p1);
    const float4 b1 = __ldcs(p1 + 1);

    float4 r;
    r.x = fmaxf(fmaxf(a0.x, a0.y), fmaxf(b0.x, b0.y));
    r.y = fmaxf(fmaxf(a0.z, a0.w), fmaxf(b0.z, b0.w));
    r.z = fmaxf(fmaxf(a1.x, a1.y), fmaxf(b1.x, b1.y));
    r.w = fmaxf(fmaxf(a1.z, a1.w), fmaxf(b1.z, b1.w));

    __stcs(out + (long long)nc * (OH * OW4) + (long long)oh * OW4 + ow4, r);
}

extern "C" void kernel_launch(void* const* d_in, const int* in_sizes, int n_in,
                              void* d_out, int out_size) {
    const float* x = (const float*)d_in[0];
    float4* out = (float4*)d_out;

    const long long total = (long long)NC * OH * OW4;  // 12,845,056
    const int threads = 256;
    const int blocks = (int)((total + threads - 1) / threads);  // 50,176

    pool2d_kernel<<<blocks, threads>>>(x, out);
}